// round 9
// baseline (speedup 1.0000x reference)
#include <cuda_runtime.h>
#include <cuda_bf16.h>

#define BB 2048
#define TT 512
#define KK 32
#define NEG_INF (-3.4e38f)
#define NCTA (148 * 16)
#define BPROWS 86   // ceil(512/6) rows of packed backpointers

__device__ unsigned g_ctr;

__global__ void crf_init() { g_ctr = 0u; }

// One warp per CTA; dynamic work queue over batch items; both recurrences in
// one loop. Backpointers packed 6 per u32 (5 bits each) to shrink smem/item
// from 17KB to ~12KB -> 16 CTAs/SM instead of 13.
__global__ __launch_bounds__(32, 16) void crf_kernel(
    const float* __restrict__ pot,     // [B,T,K]
    const float* __restrict__ trans,   // [K,K]
    const int*   __restrict__ lens,    // [B]
    const int*   __restrict__ tagidx,  // [B,T]
    float*       __restrict__ out)     // [B*T] tags, [B] best, [B] loglik
{
    const int lane = threadIdx.x;

    __shared__ unsigned bp_w[BPROWS * KK];          // packed: row=t/6, shift=(t%6)*5
    __shared__ __align__(16) float aVbuf[2][KK];
    __shared__ __align__(16) float pXbuf[2][KK];
    __shared__ __align__(16) unsigned char tags_sm[TT];

    // transitions column k (coalesced) + packed exp pairs
    float tc[KK];
#pragma unroll
    for (int j = 0; j < KK; j++) tc[j] = trans[j * KK + lane];
    unsigned long long ecp[KK / 2];
#pragma unroll
    for (int j = 0; j < KK / 2; j++) {
        float e0 = __expf(tc[2 * j]);
        float e1 = __expf(tc[2 * j + 1]);
        asm("mov.b64 %0, {%1, %2};" : "=l"(ecp[j]) : "f"(e0), "f"(e1));
    }

    for (;;) {
        unsigned b = 0;
        if (lane == 0) b = atomicAdd(&g_ctr, 1u);
        b = __shfl_sync(0xffffffffu, b, 0);
        if (b >= BB) break;

        const int len = lens[b];
        const float* pb = pot + (size_t)b * (TT * KK);

        float aV = pb[lane];
        float aF = aV;
        float mcur = __shfl_sync(0xffffffffu, aF, 0);

        // prefetch ring, depth 4 (rows 1..4 in-bounds, TT=512)
        float q0 = pb[1 * KK + lane];
        float q1 = pb[2 * KK + lane];
        float q2 = pb[3 * KK + lane];
        float q3 = pb[4 * KK + lane];

        // packed-bp accumulator state (first step is t=1: row 0, shift 5)
        unsigned bpacc = 0;
        int      bpsh  = 5;
        unsigned bpoff = lane;          // word index into bp_w for current row

        auto step = [&](float pt, int buf) {
            float pexp = __expf(aF - mcur);
            aVbuf[buf][lane] = aV;
            pXbuf[buf][lane] = pexp;
            __syncwarp();
            const float4* a4 = (const float4*)aVbuf[buf];

            float m0 = NEG_INF, m1 = NEG_INF, m2 = NEG_INF, m3 = NEG_INF;
            int   i0 = 0, i1 = 0, i2 = 0, i3 = 0;
#pragma unroll
            for (int q = 0; q < 8; q++) {
                float4 a = a4[q];
                float v0 = a.x + tc[4*q+0];
                float v1 = a.y + tc[4*q+1];
                float v2 = a.z + tc[4*q+2];
                float v3 = a.w + tc[4*q+3];
                bool g0 = v0 > m0; i0 = g0 ? (4*q+0) : i0; m0 = g0 ? v0 : m0;
                bool g1 = v1 > m1; i1 = g1 ? (4*q+1) : i1; m1 = g1 ? v1 : m1;
                bool g2 = v2 > m2; i2 = g2 ? (4*q+2) : i2; m2 = g2 ? v2 : m2;
                bool g3 = v3 > m3; i3 = g3 ? (4*q+3) : i3; m3 = g3 ? v3 : m3;
            }
            float best = m0; int arg = i0;
            bool c1 = (m1 > best) || ((m1 == best) && (i1 < arg));
            arg = c1 ? i1 : arg;  best = c1 ? m1 : best;
            bool c2 = (m2 > best) || ((m2 == best) && (i2 < arg));
            arg = c2 ? i2 : arg;  best = c2 ? m2 : best;
            bool c3 = (m3 > best) || ((m3 == best) && (i3 < arg));
            arg = c3 ? i3 : arg;  best = c3 ? m3 : best;

            // forward inner product: packed f32x2 FFMA over pXbuf
            unsigned pxa = (unsigned)__cvta_generic_to_shared(&pXbuf[buf][0]);
            unsigned long long s0, s1, pa, pb2;
            asm volatile("ld.shared.v2.b64 {%0,%1}, [%2];"
                         : "=l"(pa), "=l"(pb2) : "r"(pxa));
            asm("mul.rn.f32x2 %0, %1, %2;" : "=l"(s0) : "l"(pa),  "l"(ecp[0]));
            asm("mul.rn.f32x2 %0, %1, %2;" : "=l"(s1) : "l"(pb2), "l"(ecp[1]));
#pragma unroll
            for (int q = 1; q < 8; q++) {
                asm volatile("ld.shared.v2.b64 {%0,%1}, [%2];"
                             : "=l"(pa), "=l"(pb2) : "r"(pxa + q * 16));
                asm("fma.rn.f32x2 %0, %1, %2, %3;"
                    : "=l"(s0) : "l"(pa),  "l"(ecp[2*q+0]), "l"(s0));
                asm("fma.rn.f32x2 %0, %1, %2, %3;"
                    : "=l"(s1) : "l"(pb2), "l"(ecp[2*q+1]), "l"(s1));
            }
            asm("add.rn.f32x2 %0, %1, %2;" : "=l"(s0) : "l"(s0), "l"(s1));
            unsigned lo, hi;
            asm("mov.b64 {%0,%1}, %2;" : "=r"(lo), "=r"(hi) : "l"(s0));
            float ssum = __uint_as_float(lo) + __uint_as_float(hi);

            // pack backpointer (5 bits), flush every 6 steps
            bpacc |= (unsigned)arg << bpsh;
            bpsh += 5;
            bool full = (bpsh == 30);
            if (full) bp_w[bpoff] = bpacc;
            bpoff = full ? (bpoff + KK) : bpoff;
            bpacc = full ? 0u : bpacc;
            bpsh  = full ? 0  : bpsh;

            aV = pt + best;
            aF = pt + (mcur + __logf(ssum));
            mcur = __shfl_sync(0xffffffffu, aF, 0);
        };

        int t = 1;
        for (; t + 3 < len; t += 4) {
            int c4 = min(t + 4, TT - 1), c5 = min(t + 5, TT - 1);
            int c6 = min(t + 6, TT - 1), c7 = min(t + 7, TT - 1);
            float n0 = pb[c4 * KK + lane];
            float n1 = pb[c5 * KK + lane];
            float n2 = pb[c6 * KK + lane];
            float n3 = pb[c7 * KK + lane];
            step(q0, 1);
            step(q1, 0);
            step(q2, 1);
            step(q3, 0);
            q0 = n0; q1 = n1; q2 = n2; q3 = n3;
        }
        if (t < len) { step(q0, 1); t++; }
        if (t < len) { step(q1, 0); t++; }
        if (t < len) { step(q2, 1); }
        if (bpsh != 0) bp_w[bpoff] = bpacc;   // flush partial row
        __syncwarp();

        // ---- Viterbi terminal: best_score + last_tag (first max index) ----
        float mv = aV;
#pragma unroll
        for (int s = 16; s; s >>= 1)
            mv = fmaxf(mv, __shfl_xor_sync(0xffffffffu, mv, s));
        unsigned msk = __ballot_sync(0xffffffffu, aV == mv);
        int last_tag = __ffs(msk) - 1;

        // ---- exact final logsumexp ----
        float mf = aF;
#pragma unroll
        for (int s = 16; s; s >>= 1)
            mf = fmaxf(mf, __shfl_xor_sync(0xffffffffu, mf, s));
        float ex = __expf(aF - mf);
#pragma unroll
        for (int s = 16; s; s >>= 1)
            ex += __shfl_xor_sync(0xffffffffu, ex, s);
        float log_norm = mf + __logf(ex);

        // ---- tags: fill with last_tag, then backtrace over packed bp ----
        unsigned rep = (unsigned)last_tag * 0x01010101u;
#pragma unroll
        for (int w = 0; w < 4; w++)
            ((unsigned*)tags_sm)[w * 32 + lane] = rep;
        __syncwarp();

        if (lane == 0) {
            int tg = last_tag;
            for (int tt = len - 1; tt >= 1; tt--) {
                unsigned w = bp_w[(tt / 6) * KK + tg];
                tg = (int)((w >> ((tt % 6) * 5)) & 31u);
                tags_sm[tt - 1] = (unsigned char)tg;
            }
        }
        __syncwarp();

        float* otags = out + (size_t)b * TT;
#pragma unroll
        for (int c = 0; c < 4; c++) {
            uchar4 u = ((const uchar4*)tags_sm)[c * 32 + lane];
            ((float4*)otags)[c * 32 + lane] =
                make_float4((float)u.x, (float)u.y, (float)u.z, (float)u.w);
        }

        // ---- gold sequence score (branch-free) ----
        const int* ti = tagidx + (size_t)b * TT;
        float acc = 0.f;
#pragma unroll 4
        for (int tt = lane; tt < TT; tt += 32) {
            int tg = ti[tt];
            float u  = pb[tt * KK + tg];
            int   tn = ti[min(tt + 1, TT - 1)];
            float w  = trans[tg * KK + tn];
            acc += (tt < len)     ? u : 0.f;
            acc += (tt < len - 1) ? w : 0.f;
        }
#pragma unroll
        for (int s = 16; s; s >>= 1)
            acc += __shfl_xor_sync(0xffffffffu, acc, s);

        if (lane == 0) {
            out[(size_t)BB * TT + b]      = mv;               // best_score
            out[(size_t)BB * TT + BB + b] = acc - log_norm;   // log_likelihood
        }
    }
}

extern "C" void kernel_launch(void* const* d_in, const int* in_sizes, int n_in,
                              void* d_out, int out_size) {
    const float* pot = nullptr;
    const float* trn = nullptr;
    const int*   len = nullptr;
    const int*   tgi = nullptr;
    for (int i = 0; i < n_in; i++) {
        switch (in_sizes[i]) {
            case 33554432: pot = (const float*)d_in[i]; break;
            case 1024:     trn = (const float*)d_in[i]; break;
            case 2048:     len = (const int*)d_in[i];   break;
            case 1048576:  tgi = (const int*)d_in[i];   break;
            default: break;
        }
    }
    float* out = (float*)d_out;
    crf_init<<<1, 1>>>();
    crf_kernel<<<NCTA, 32>>>(pot, trn, len, tgi, out);
    (void)out_size;
}

// round 10
// speedup vs baseline: 1.3923x; 1.3923x over previous
#include <cuda_runtime.h>
#include <cuda_bf16.h>

#define BB 2048
#define TT 512
#define KK 32
#define NEG_INF (-3.4e38f)
#define NCTA (148 * 13)

__device__ unsigned g_ctr;

__global__ void crf_init() { g_ctr = 0u; }

// One warp per CTA; dynamic queue over batch items; both recurrences fused.
// f32x2 packed math for the Viterbi adds and forward FFMAs (4 accumulator
// chains); forward normalizer is a 2-step-lagged aF[0] so the SHFL is off the
// critical path. Final logsumexp is exact, argmax semantics bit-identical.
__global__ __launch_bounds__(32) void crf_kernel(
    const float* __restrict__ pot,     // [B,T,K]
    const float* __restrict__ trans,   // [K,K]
    const int*   __restrict__ lens,    // [B]
    const int*   __restrict__ tagidx,  // [B,T]
    float*       __restrict__ out)     // [B*T] tags, [B] best, [B] loglik
{
    const int lane = threadIdx.x;

    __shared__ unsigned char bp_sm[TT * KK];
    __shared__ __align__(16) float aVbuf[2][KK];
    __shared__ __align__(16) float pXbuf[2][KK];
    __shared__ __align__(16) unsigned char tags_sm[TT];

    // transitions column k packed as (t_j, t_j+1) pairs; same for exp
    unsigned long long tcp[KK / 2], ecp[KK / 2];
#pragma unroll
    for (int j = 0; j < KK / 2; j++) {
        float t0 = trans[(2 * j)     * KK + lane];
        float t1 = trans[(2 * j + 1) * KK + lane];
        asm("mov.b64 %0, {%1, %2};" : "=l"(tcp[j]) : "f"(t0), "f"(t1));
        float e0 = __expf(t0);
        float e1 = __expf(t1);
        asm("mov.b64 %0, {%1, %2};" : "=l"(ecp[j]) : "f"(e0), "f"(e1));
    }

    for (;;) {
        unsigned b = 0;
        if (lane == 0) b = atomicAdd(&g_ctr, 1u);
        b = __shfl_sync(0xffffffffu, b, 0);
        if (b >= BB) break;

        const int len = lens[b];
        const float* pb = pot + (size_t)b * (TT * KK);

        float aV = pb[lane];
        float aF = aV;
        float mB = __shfl_sync(0xffffffffu, aF, 0);
        float mA = mB;

        // prefetch ring, depth 4 (rows 1..4 in-bounds, TT=512)
        float q0 = pb[1 * KK + lane];
        float q1 = pb[2 * KK + lane];
        float q2 = pb[3 * KK + lane];
        float q3 = pb[4 * KK + lane];

        auto step = [&](float pt, int t, int buf) {
            float pexp = __expf(aF - mA);
            aVbuf[buf][lane] = aV;
            pXbuf[buf][lane] = pexp;
            __syncwarp();
            unsigned abase = (unsigned)__cvta_generic_to_shared(&aVbuf[buf][0]);
            unsigned pbase = (unsigned)__cvta_generic_to_shared(&pXbuf[buf][0]);

            float m0 = NEG_INF, m1 = NEG_INF, m2 = NEG_INF, m3 = NEG_INF;
            int   i0 = 0, i1 = 0, i2 = 0, i3 = 0;
            unsigned long long s0, s1, s2, s3;
#pragma unroll
            for (int q = 0; q < 8; q++) {
                // ---- Viterbi: packed adds, scalar cmp/sel (exact) ----
                unsigned long long va, vb;
                asm volatile("ld.shared.v2.b64 {%0,%1}, [%2];"
                             : "=l"(va), "=l"(vb) : "r"(abase + q * 16));
                asm("add.rn.f32x2 %0, %1, %2;" : "=l"(va) : "l"(va), "l"(tcp[2*q+0]));
                asm("add.rn.f32x2 %0, %1, %2;" : "=l"(vb) : "l"(vb), "l"(tcp[2*q+1]));
                float v0, v1, v2, v3;
                asm("mov.b64 {%0, %1}, %2;" : "=f"(v0), "=f"(v1) : "l"(va));
                asm("mov.b64 {%0, %1}, %2;" : "=f"(v2), "=f"(v3) : "l"(vb));
                bool g0 = v0 > m0; i0 = g0 ? (4*q+0) : i0; m0 = g0 ? v0 : m0;
                bool g1 = v1 > m1; i1 = g1 ? (4*q+1) : i1; m1 = g1 ? v1 : m1;
                bool g2 = v2 > m2; i2 = g2 ? (4*q+2) : i2; m2 = g2 ? v2 : m2;
                bool g3 = v3 > m3; i3 = g3 ? (4*q+3) : i3; m3 = g3 ? v3 : m3;

                // ---- forward: packed FFMA, 4 accumulator chains ----
                unsigned long long pa, pc;
                asm volatile("ld.shared.v2.b64 {%0,%1}, [%2];"
                             : "=l"(pa), "=l"(pc) : "r"(pbase + q * 16));
                if (q == 0) {
                    asm("mul.rn.f32x2 %0, %1, %2;" : "=l"(s0) : "l"(pa), "l"(ecp[0]));
                    asm("mul.rn.f32x2 %0, %1, %2;" : "=l"(s1) : "l"(pc), "l"(ecp[1]));
                } else if (q == 1) {
                    asm("mul.rn.f32x2 %0, %1, %2;" : "=l"(s2) : "l"(pa), "l"(ecp[2]));
                    asm("mul.rn.f32x2 %0, %1, %2;" : "=l"(s3) : "l"(pc), "l"(ecp[3]));
                } else if ((q & 1) == 0) {
                    asm("fma.rn.f32x2 %0, %1, %2, %3;"
                        : "=l"(s0) : "l"(pa), "l"(ecp[2*q+0]), "l"(s0));
                    asm("fma.rn.f32x2 %0, %1, %2, %3;"
                        : "=l"(s1) : "l"(pc), "l"(ecp[2*q+1]), "l"(s1));
                } else {
                    asm("fma.rn.f32x2 %0, %1, %2, %3;"
                        : "=l"(s2) : "l"(pa), "l"(ecp[2*q+0]), "l"(s2));
                    asm("fma.rn.f32x2 %0, %1, %2, %3;"
                        : "=l"(s3) : "l"(pc), "l"(ecp[2*q+1]), "l"(s3));
                }
            }
            // cross-chain argmax combine (value-tie -> min index; exact)
            float best = m0; int arg = i0;
            bool c1 = (m1 > best) || ((m1 == best) && (i1 < arg));
            arg = c1 ? i1 : arg;  best = c1 ? m1 : best;
            bool c2 = (m2 > best) || ((m2 == best) && (i2 < arg));
            arg = c2 ? i2 : arg;  best = c2 ? m2 : best;
            bool c3 = (m3 > best) || ((m3 == best) && (i3 < arg));
            arg = c3 ? i3 : arg;  best = c3 ? m3 : best;

            // reduce forward accumulators
            asm("add.rn.f32x2 %0, %1, %2;" : "=l"(s0) : "l"(s0), "l"(s2));
            asm("add.rn.f32x2 %0, %1, %2;" : "=l"(s1) : "l"(s1), "l"(s3));
            asm("add.rn.f32x2 %0, %1, %2;" : "=l"(s0) : "l"(s0), "l"(s1));
            float slo, shi;
            asm("mov.b64 {%0, %1}, %2;" : "=f"(slo), "=f"(shi) : "l"(s0));
            float ssum = slo + shi;

            bp_sm[t * KK + lane] = (unsigned char)arg;
            aV = pt + best;
            aF = pt + (mA + __logf(ssum));
            mA = mB;                                   // 2-step-lagged offset
            mB = __shfl_sync(0xffffffffu, aF, 0);      // latency hidden 1 step
        };

        int t = 1;
        for (; t + 3 < len; t += 4) {
            int c4 = min(t + 4, TT - 1), c5 = min(t + 5, TT - 1);
            int c6 = min(t + 6, TT - 1), c7 = min(t + 7, TT - 1);
            float n0 = pb[c4 * KK + lane];
            float n1 = pb[c5 * KK + lane];
            float n2 = pb[c6 * KK + lane];
            float n3 = pb[c7 * KK + lane];
            step(q0, t + 0, 1);
            step(q1, t + 1, 0);
            step(q2, t + 2, 1);
            step(q3, t + 3, 0);
            q0 = n0; q1 = n1; q2 = n2; q3 = n3;
        }
        if (t < len) { step(q0, t, 1); t++; }
        if (t < len) { step(q1, t, 0); t++; }
        if (t < len) { step(q2, t, 1); }
        __syncwarp();

        // ---- Viterbi terminal: best_score + last_tag (first max index) ----
        float mv = aV;
#pragma unroll
        for (int s = 16; s; s >>= 1)
            mv = fmaxf(mv, __shfl_xor_sync(0xffffffffu, mv, s));
        unsigned msk = __ballot_sync(0xffffffffu, aV == mv);
        int last_tag = __ffs(msk) - 1;

        // ---- exact final logsumexp ----
        float mf = aF;
#pragma unroll
        for (int s = 16; s; s >>= 1)
            mf = fmaxf(mf, __shfl_xor_sync(0xffffffffu, mf, s));
        float ex = __expf(aF - mf);
#pragma unroll
        for (int s = 16; s; s >>= 1)
            ex += __shfl_xor_sync(0xffffffffu, ex, s);
        float log_norm = mf + __logf(ex);

        // ---- tags: fill with last_tag, then backtrace over smem ----
        unsigned rep = (unsigned)last_tag * 0x01010101u;
#pragma unroll
        for (int w = 0; w < 4; w++)
            ((unsigned*)tags_sm)[w * 32 + lane] = rep;
        __syncwarp();

        if (lane == 0) {
            int tg = last_tag;
            for (int tt = len - 1; tt >= 1; tt--) {
                tg = bp_sm[tt * KK + tg];
                tags_sm[tt - 1] = (unsigned char)tg;
            }
        }
        __syncwarp();

        float* otags = out + (size_t)b * TT;
#pragma unroll
        for (int c = 0; c < 4; c++) {
            uchar4 u = ((const uchar4*)tags_sm)[c * 32 + lane];
            ((float4*)otags)[c * 32 + lane] =
                make_float4((float)u.x, (float)u.y, (float)u.z, (float)u.w);
        }

        // ---- gold sequence score (branch-free) ----
        const int* ti = tagidx + (size_t)b * TT;
        float acc = 0.f;
#pragma unroll 4
        for (int tt = lane; tt < TT; tt += 32) {
            int tg = ti[tt];
            float u  = pb[tt * KK + tg];
            int   tn = ti[min(tt + 1, TT - 1)];
            float w  = trans[tg * KK + tn];
            acc += (tt < len)     ? u : 0.f;
            acc += (tt < len - 1) ? w : 0.f;
        }
#pragma unroll
        for (int s = 16; s; s >>= 1)
            acc += __shfl_xor_sync(0xffffffffu, acc, s);

        if (lane == 0) {
            out[(size_t)BB * TT + b]      = mv;               // best_score
            out[(size_t)BB * TT + BB + b] = acc - log_norm;   // log_likelihood
        }
    }
}

extern "C" void kernel_launch(void* const* d_in, const int* in_sizes, int n_in,
                              void* d_out, int out_size) {
    const float* pot = nullptr;
    const float* trn = nullptr;
    const int*   len = nullptr;
    const int*   tgi = nullptr;
    for (int i = 0; i < n_in; i++) {
        switch (in_sizes[i]) {
            case 33554432: pot = (const float*)d_in[i]; break;
            case 1024:     trn = (const float*)d_in[i]; break;
            case 2048:     len = (const int*)d_in[i];   break;
            case 1048576:  tgi = (const int*)d_in[i];   break;
            default: break;
        }
    }
    float* out = (float*)d_out;
    crf_init<<<1, 1>>>();
    crf_kernel<<<NCTA, 32>>>(pot, trn, len, tgi, out);
    (void)out_size;
}